// round 5
// baseline (speedup 1.0000x reference)
#include <cuda_runtime.h>

#define NN 50000
#define EE 800000
#define DD 64
#define GG 64

// ---------------- scratch (device globals; accessed ONLY by symbol in device code)
__device__ int   d_is64;
__device__ int   d_col[EE];
__device__ int   d_row[EE];
__device__ int   d_batch[NN];
__device__ int   d_deg[NN];
__device__ int   d_rowptr[NN + 1];
__device__ int   d_cursor[NN];
__device__ int   d_csrcol[EE];
__device__ float d_csrval[EE];
__device__ int   d_degmaxbits[GG];     // per-graph max degree, float bits (degree >= 0)
__device__ float d_e0[NN * DD];        // x_emb ping
__device__ float d_e1[NN * DD];        // x_emb pong
__device__ float d_nein[NN * DD];      // [0:62] relu node_edge embed, [63] degree_norm
__device__ float d_xaggemb[NN * DD];   // x_agg_emb
__device__ float d_gsum[GG * DD];
__device__ int   d_gcnt[GG];
__device__ float d_rg[GG * DD];        // relu(g_agg @ W_g + b_g)

// ---------------- setup -----------------------------------------------------

__global__ void k_zero() {
    int i = blockIdx.x * blockDim.x + threadIdx.x;
    int st = gridDim.x * blockDim.x;
    if (i == 0) d_is64 = 1;
    for (int j = i; j < NN; j += st) d_deg[j] = 0;
    for (int j = i; j < GG; j += st) { d_degmaxbits[j] = 0; d_gcnt[j] = 0; }
    for (int j = i; j < GG * DD; j += st) d_gsum[j] = 0.f;
}

// int64 vs int32 sniff: reading EE int64 from a 2*EE-int32 buffer is exactly
// in-bounds; int32 data reinterpreted as int64 is guaranteed out of [0,NN)
// somewhere among 800k elements.
__global__ void k_detect(const long long* __restrict__ ei) {
    int e = blockIdx.x * blockDim.x + threadIdx.x;
    if (e < EE) {
        long long v = ei[e];
        if (v < 0 || v >= NN) d_is64 = 0;
    }
}

__global__ void k_cvt(const void* __restrict__ ei, const void* __restrict__ bt) {
    int i = blockIdx.x * blockDim.x + threadIdx.x;
    int s = d_is64;
    if (i < EE) {
        if (s) {
            d_col[i] = (int)((const long long*)ei)[i];
            d_row[i] = (int)((const long long*)ei)[EE + i];
        } else {
            d_col[i] = ((const int*)ei)[i];
            d_row[i] = ((const int*)ei)[EE + i];
        }
    }
    if (i < NN)
        d_batch[i] = s ? (int)((const long long*)bt)[i] : ((const int*)bt)[i];
}

__global__ void k_count(const float* __restrict__ degree) {
    int i = blockIdx.x * blockDim.x + threadIdx.x;
    if (i < EE) atomicAdd(&d_deg[d_row[i]], 1);
    if (i < NN) atomicMax(&d_degmaxbits[d_batch[i]], __float_as_int(degree[i]));
}

// single-block exclusive scan deg -> rowptr (+cursor)
__global__ void k_scan() {
    __shared__ int ssum[1024];
    int t = threadIdx.x;
    const int per = (NN + 1023) / 1024;
    int base = t * per;
    int s = 0;
    for (int i = 0; i < per; i++) { int idx = base + i; if (idx < NN) s += d_deg[idx]; }
    ssum[t] = s;
    __syncthreads();
    for (int off = 1; off < 1024; off <<= 1) {
        int v = 0;
        if (t >= off) v = ssum[t - off];
        __syncthreads();
        if (t >= off) ssum[t] += v;
        __syncthreads();
    }
    int run = (t == 0) ? 0 : ssum[t - 1];
    for (int i = 0; i < per; i++) {
        int idx = base + i;
        if (idx < NN) { d_rowptr[idx] = run; d_cursor[idx] = run; run += d_deg[idx]; }
    }
    if (t == 0) d_rowptr[NN] = EE;
}

__global__ void k_fill(const float* __restrict__ ea) {
    int e = blockIdx.x * blockDim.x + threadIdx.x;
    if (e >= EE) return;
    int r = d_row[e];
    int p = atomicAdd(&d_cursor[r], 1);
    d_csrcol[p] = d_col[e];
    d_csrval[p] = ea[e];
}

// ---------------- embeddings -------------------------------------------------

// x_emb = relu(x @ W_en + b_en) -> d_e0
__global__ void k_xemb(const float* __restrict__ x, const float* __restrict__ W,
                       const float* __restrict__ b) {
    int i = blockIdx.x * blockDim.x + threadIdx.x;
    if (i >= NN * DD) return;
    int n = i >> 6, c = i & 63;
    const float* xr = x + n * 7;
    float s = b[c];
#pragma unroll
    for (int k = 0; k < 7; k++) s += xr[k] * W[k * DD + c];
    d_e0[i] = fmaxf(s, 0.f);
}

// node+edge embed: warp per node; mean of [x[col](7), edge_attr(1)] -> GEMV 8x63 relu
// d_nein[n][0:62] = relu result; [63] = degree_norm (per-graph deg max)
__global__ void k_ne(const float* __restrict__ x, const float* __restrict__ W,
                     const float* __restrict__ b) {
    int warp = (blockIdx.x * blockDim.x + threadIdx.x) >> 5;
    int lane = threadIdx.x & 31;
    if (warp >= NN) return;
    int n = warp;
    int beg = d_rowptr[n], end = d_rowptr[n + 1];
    float acc[8] = {0, 0, 0, 0, 0, 0, 0, 0};
    for (int j = beg + lane; j < end; j += 32) {
        int c = d_csrcol[j];
        const float* xr = x + c * 7;
#pragma unroll
        for (int k = 0; k < 7; k++) acc[k] += xr[k];
        acc[7] += d_csrval[j];
    }
#pragma unroll
    for (int k = 0; k < 8; k++)
#pragma unroll
        for (int off = 16; off; off >>= 1) acc[k] += __shfl_xor_sync(0xffffffffu, acc[k], off);
    float inv = 1.f / (float)max(end - beg, 1);
#pragma unroll
    for (int k = 0; k < 8; k++) acc[k] *= inv;
    float o0 = b[lane];
    float o1 = (lane < 31) ? b[lane + 32] : 0.f;
#pragma unroll
    for (int k = 0; k < 8; k++) {
        o0 += acc[k] * W[k * 63 + lane];
        if (lane < 31) o1 += acc[k] * W[k * 63 + lane + 32];
    }
    d_nein[n * DD + lane] = fmaxf(o0, 0.f);
    if (lane < 31) d_nein[n * DD + 32 + lane] = fmaxf(o1, 0.f);
    if (lane == 31) d_nein[n * DD + 63] = __int_as_float(d_degmaxbits[d_batch[n]]);
}

// x_agg_emb = relu([node_edge, degree_norm] @ W_agg + b_agg)
__global__ void k_aggemb(const float* __restrict__ W, const float* __restrict__ b) {
    int i = blockIdx.x * blockDim.x + threadIdx.x;
    if (i >= NN * DD) return;
    int n = i >> 6, c = i & 63;
    const float* in = d_nein + n * DD;
    float s = b[c];
#pragma unroll
    for (int k = 0; k < DD; k++) s += in[k] * W[k * DD + c];
    d_xaggemb[i] = fmaxf(s, 0.f);
}

// ---------------- fused message-passing layer -------------------------------
// 256 thr = 8 warps; warp owns 4 nodes (amortizes smem weight reads 4x)
// dyn smem: Wm 32KB + Wu 32KB + staging 16KB = 80KB

#define NPW 4
#define LAYER_SMEM ((8192 + 8192 + 8 * NPW * 128) * (int)sizeof(float))

__global__ void __launch_bounds__(256) k_layer(
    int flip,   // 0: e0 -> e1 ; 1: e1 -> e0
    const float* __restrict__ Wm, const float* __restrict__ bm,
    const float* __restrict__ Wu, const float* __restrict__ bu) {
    const float* xin = flip ? d_e1 : d_e0;   // device-side symbol -> real device address
    float*       xout = flip ? d_e0 : d_e1;
    extern __shared__ float sm[];
    float* sWm = sm;
    float* sWu = sm + 8192;
    float* sIn = sm + 16384;
    int t = threadIdx.x;
    for (int i = t; i < 8192; i += 256) { sWm[i] = Wm[i]; sWu[i] = Wu[i]; }
    __syncthreads();

    int warp = t >> 5, lane = t & 31;
    float* sv = sIn + warp * (NPW * 128);
    int nbase = blockIdx.x * (8 * NPW) + warp * NPW;

    // Phase A: x_agg = mean_{e->n} ea[e]*xin[col[e]]; stage [x_agg, x_agg_emb]
#pragma unroll
    for (int i = 0; i < NPW; i++) {
        int n = nbase + i;
        if (n < NN) {
            int beg = d_rowptr[n], end = d_rowptr[n + 1];
            float a0 = 0.f, a1 = 0.f;
            for (int j = beg; j < end; j++) {
                int c = d_csrcol[j];
                float w = d_csrval[j];
                const float* xr = xin + c * DD;
                a0 += w * xr[lane];
                a1 += w * xr[lane + 32];
            }
            float inv = 1.f / (float)max(end - beg, 1);
            sv[i * 128 + lane]      = a0 * inv;
            sv[i * 128 + 32 + lane] = a1 * inv;
            sv[i * 128 + 64 + lane] = d_xaggemb[n * DD + lane];
            sv[i * 128 + 96 + lane] = d_xaggemb[n * DD + 32 + lane];
        } else {
            sv[i * 128 + lane] = 0.f; sv[i * 128 + 32 + lane] = 0.f;
            sv[i * 128 + 64 + lane] = 0.f; sv[i * 128 + 96 + lane] = 0.f;
        }
    }
    __syncwarp();

    // Phase B: m = relu([x_agg, x_agg_emb] @ Wm + bm)
    float m0[NPW], m1[NPW];
    {
        float b0 = bm[lane], b1 = bm[lane + 32];
#pragma unroll
        for (int i = 0; i < NPW; i++) { m0[i] = b0; m1[i] = b1; }
    }
#pragma unroll 4
    for (int k = 0; k < 128; k++) {
        float w0 = sWm[k * DD + lane];
        float w1 = sWm[k * DD + lane + 32];
#pragma unroll
        for (int i = 0; i < NPW; i++) {
            float v = sv[i * 128 + k];
            m0[i] += v * w0;
            m1[i] += v * w1;
        }
    }
    __syncwarp();

    // Phase C: stage [x_emb_old, relu(m)]
#pragma unroll
    for (int i = 0; i < NPW; i++) {
        int n = nbase + i;
        if (n < NN) {
            sv[i * 128 + lane]      = xin[n * DD + lane];
            sv[i * 128 + 32 + lane] = xin[n * DD + 32 + lane];
        } else {
            sv[i * 128 + lane] = 0.f; sv[i * 128 + 32 + lane] = 0.f;
        }
        sv[i * 128 + 64 + lane] = fmaxf(m0[i], 0.f);
        sv[i * 128 + 96 + lane] = fmaxf(m1[i], 0.f);
    }
    __syncwarp();

    // Phase D: x_emb_new = relu([x_emb, m] @ Wu + bu)
    float u0[NPW], u1[NPW];
    {
        float b0 = bu[lane], b1 = bu[lane + 32];
#pragma unroll
        for (int i = 0; i < NPW; i++) { u0[i] = b0; u1[i] = b1; }
    }
#pragma unroll 4
    for (int k = 0; k < 128; k++) {
        float w0 = sWu[k * DD + lane];
        float w1 = sWu[k * DD + lane + 32];
#pragma unroll
        for (int i = 0; i < NPW; i++) {
            float v = sv[i * 128 + k];
            u0[i] += v * w0;
            u1[i] += v * w1;
        }
    }
#pragma unroll
    for (int i = 0; i < NPW; i++) {
        int n = nbase + i;
        if (n < NN) {
            xout[n * DD + lane]      = fmaxf(u0[i], 0.f);
            xout[n * DD + 32 + lane] = fmaxf(u1[i], 0.f);
        }
    }
}

// ---------------- readout ----------------------------------------------------

// per-graph sums, smem-staged (batch sorted -> low contention); final x_emb in d_e1
__global__ void k_gsum() {
    __shared__ float sg[GG * DD];
    __shared__ int sc[GG];
    int t = threadIdx.x;
    for (int i = t; i < GG * DD; i += blockDim.x) sg[i] = 0.f;
    for (int i = t; i < GG; i += blockDim.x) sc[i] = 0;
    __syncthreads();
    int per = (NN + gridDim.x - 1) / gridDim.x;
    int nb = blockIdx.x * per;
    int ne = min(NN, nb + per);
    int col = t & 63, sub = t >> 6;
    for (int n = nb + sub; n < ne; n += 4) {
        int g = d_batch[n];
        atomicAdd(&sg[g * DD + col], d_e1[n * DD + col]);
        if (col == 0) atomicAdd(&sc[g], 1);
    }
    __syncthreads();
    for (int i = t; i < GG * DD; i += blockDim.x) atomicAdd(&d_gsum[i], sg[i]);
    for (int i = t; i < GG; i += blockDim.x) atomicAdd(&d_gcnt[i], sc[i]);
}

// rg = relu((gsum/count) @ W_g + b_g)
__global__ void k_gproj(const float* __restrict__ Wg, const float* __restrict__ bg) {
    int g = blockIdx.x, c = threadIdx.x;
    float inv = 1.f / (float)max(d_gcnt[g], 1);
    float s = bg[c];
    const float* row = d_gsum + g * DD;
#pragma unroll
    for (int k = 0; k < DD; k++) s += row[k] * inv * Wg[k * DD + c];
    d_rg[g * DD + c] = fmaxf(s, 0.f);
}

// q[n] = b_r + rg[batch[n]] . Wr[0:64] + x_emb[n] . Wr[64:128]  (x_emb >= 0)
__global__ void k_final(const float* __restrict__ Wr, const float* __restrict__ br,
                        float* __restrict__ out) {
    int warp = (blockIdx.x * blockDim.x + threadIdx.x) >> 5;
    int lane = threadIdx.x & 31;
    if (warp >= NN) return;
    int n = warp;
    int g = d_batch[n];
    const float* rg = d_rg + g * DD;
    const float* xr = d_e1 + n * DD;
    float p = rg[lane] * Wr[lane] + rg[lane + 32] * Wr[lane + 32]
            + xr[lane] * Wr[64 + lane] + xr[lane + 32] * Wr[96 + lane];
#pragma unroll
    for (int off = 16; off; off >>= 1) p += __shfl_xor_sync(0xffffffffu, p, off);
    if (lane == 0) out[n] = p + br[0];
}

// ---------------- launch ------------------------------------------------------

extern "C" void kernel_launch(void* const* d_in, const int* in_sizes, int n_in,
                              void* d_out, int out_size) {
    // inputs: x, edge_index, edge_attr, batch, degree, [num_graphs], weights...
    int base = (n_in > 5 && in_sizes[5] == 1) ? 6 : 5;

    const float* x      = (const float*)d_in[0];
    const void*  ei     = d_in[1];
    const float* ea     = (const float*)d_in[2];
    const void*  batch  = d_in[3];
    const float* degree = (const float*)d_in[4];
    const float* W_en  = (const float*)d_in[base + 0];
    const float* b_en  = (const float*)d_in[base + 1];
    const float* W_ene = (const float*)d_in[base + 2];
    const float* b_ene = (const float*)d_in[base + 3];
    const float* W_agg = (const float*)d_in[base + 4];
    const float* b_agg = (const float*)d_in[base + 5];
    const float* Wm    = (const float*)d_in[base + 6];
    const float* bm    = (const float*)d_in[base + 7];
    const float* Wu    = (const float*)d_in[base + 8];
    const float* bu    = (const float*)d_in[base + 9];
    const float* W_g   = (const float*)d_in[base + 10];
    const float* b_g   = (const float*)d_in[base + 11];
    const float* W_r   = (const float*)d_in[base + 12];
    const float* b_r   = (const float*)d_in[base + 13];
    float* out = (float*)d_out;

    cudaFuncSetAttribute(k_layer, cudaFuncAttributeMaxDynamicSharedMemorySize, LAYER_SMEM);

    const int TB = 256;
    int gE  = (EE + TB - 1) / TB;
    int gND = (NN * DD + TB - 1) / TB;
    int gNW = (NN * 32 + TB - 1) / TB;   // warp-per-node grids

    k_zero<<<64, TB>>>();
    k_detect<<<gE, TB>>>((const long long*)ei);
    k_cvt<<<gE, TB>>>(ei, batch);
    k_count<<<gE, TB>>>(degree);
    k_scan<<<1, 1024>>>();
    k_fill<<<gE, TB>>>(ea);

    k_xemb<<<gND, TB>>>(x, W_en, b_en);
    k_ne<<<gNW, TB>>>(x, W_ene, b_ene);
    k_aggemb<<<gND, TB>>>(W_agg, b_agg);

    int nodes_per_blk = 8 * NPW;
    int gL = (NN + nodes_per_blk - 1) / nodes_per_blk;
    k_layer<<<gL, TB, LAYER_SMEM>>>(0, Wm + 0 * 8192, bm + 0 * 64, Wu + 0 * 8192, bu + 0 * 64);
    k_layer<<<gL, TB, LAYER_SMEM>>>(1, Wm + 1 * 8192, bm + 1 * 64, Wu + 1 * 8192, bu + 1 * 64);
    k_layer<<<gL, TB, LAYER_SMEM>>>(0, Wm + 2 * 8192, bm + 2 * 64, Wu + 2 * 8192, bu + 2 * 64);

    k_gsum<<<148, TB>>>();
    k_gproj<<<GG, DD>>>(W_g, b_g);
    k_final<<<gNW, TB>>>(W_r, b_r, out);

    (void)in_sizes; (void)n_in; (void)out_size; (void)degree;
}